// round 1
// baseline (speedup 1.0000x reference)
#include <cuda_runtime.h>
#include <cuda_bf16.h>

// Problem: 6 inputs [B=8192, D=2048] fp32:
//   head_real, head_imag, rel_real, rel_imag, tail_real, tail_imag
// rot_r = hr*rr - hi*ri ; rot_i = -(hi*rr + hr*ri)
// ab = sum(rot_r*tr + rot_i*ti); aa = sum(rot_r^2 + rot_i^2); bb = sum(tr^2+ti^2)
// out[b] = ab / sqrt(aa*bb)
//
// Strictly HBM-bound: ~402.7 MB read. One CTA per row, float4 loads,
// warp shfl reduction + small shared-memory cross-warp combine.

#define D_DIM 2048
#define THREADS 256

__global__ __launch_bounds__(THREADS)
void chrono_rot_kernel(const float4* __restrict__ hr,
                       const float4* __restrict__ hi,
                       const float4* __restrict__ rr,
                       const float4* __restrict__ ri,
                       const float4* __restrict__ tr,
                       const float4* __restrict__ ti,
                       float* __restrict__ out)
{
    const int b = blockIdx.x;
    const int tid = threadIdx.x;
    const size_t base = (size_t)b * (D_DIM / 4);

    float ab = 0.f, aa = 0.f, bb = 0.f;

    // D/4 = 512 float4 per row; 256 threads -> 2 iterations, fully unrolled
    // so ptxas front-batches all 12 LDG.128 per iteration (high MLP).
    #pragma unroll
    for (int it = 0; it < (D_DIM / 4) / THREADS; ++it) {
        const size_t idx = base + tid + it * THREADS;
        const float4 HR = hr[idx];
        const float4 HI = hi[idx];
        const float4 RR = rr[idx];
        const float4 RI = ri[idx];
        const float4 TR = tr[idx];
        const float4 TI = ti[idx];

        #pragma unroll
        for (int k = 0; k < 4; ++k) {
            const float hrk = (&HR.x)[k];
            const float hik = (&HI.x)[k];
            const float rrk = (&RR.x)[k];
            const float rik = (&RI.x)[k];
            const float trk = (&TR.x)[k];
            const float tik = (&TI.x)[k];

            const float rot_r = hrk * rrk - hik * rik;
            const float rot_i = -(hik * rrk + hrk * rik);

            ab = fmaf(rot_r, trk, fmaf(rot_i, tik, ab));
            aa = fmaf(rot_r, rot_r, fmaf(rot_i, rot_i, aa));
            bb = fmaf(trk, trk, fmaf(tik, tik, bb));
        }
    }

    // Warp reduction (butterfly)
    #pragma unroll
    for (int off = 16; off > 0; off >>= 1) {
        ab += __shfl_xor_sync(0xFFFFFFFFu, ab, off);
        aa += __shfl_xor_sync(0xFFFFFFFFu, aa, off);
        bb += __shfl_xor_sync(0xFFFFFFFFu, bb, off);
    }

    __shared__ float s_ab[THREADS / 32];
    __shared__ float s_aa[THREADS / 32];
    __shared__ float s_bb[THREADS / 32];

    const int lane = tid & 31;
    const int wid  = tid >> 5;
    if (lane == 0) {
        s_ab[wid] = ab;
        s_aa[wid] = aa;
        s_bb[wid] = bb;
    }
    __syncthreads();

    if (wid == 0) {
        // THREADS/32 = 8 partials; reduce with first 8 lanes.
        float vab = (lane < THREADS / 32) ? s_ab[lane] : 0.f;
        float vaa = (lane < THREADS / 32) ? s_aa[lane] : 0.f;
        float vbb = (lane < THREADS / 32) ? s_bb[lane] : 0.f;
        #pragma unroll
        for (int off = 4; off > 0; off >>= 1) {
            vab += __shfl_xor_sync(0xFFFFFFFFu, vab, off);
            vaa += __shfl_xor_sync(0xFFFFFFFFu, vaa, off);
            vbb += __shfl_xor_sync(0xFFFFFFFFu, vbb, off);
        }
        if (lane == 0) {
            out[b] = vab * rsqrtf(vaa * vbb);
        }
    }
}

extern "C" void kernel_launch(void* const* d_in, const int* in_sizes, int n_in,
                              void* d_out, int out_size)
{
    const float4* hr = (const float4*)d_in[0];
    const float4* hi = (const float4*)d_in[1];
    const float4* rr = (const float4*)d_in[2];
    const float4* ri = (const float4*)d_in[3];
    const float4* tr = (const float4*)d_in[4];
    const float4* ti = (const float4*)d_in[5];
    float* out = (float*)d_out;

    const int B = in_sizes[0] / D_DIM;  // 8192
    chrono_rot_kernel<<<B, THREADS>>>(hr, hi, rr, ri, tr, ti, out);
}